// round 1
// baseline (speedup 1.0000x reference)
#include <cuda_runtime.h>
#include <math.h>

#define EPS   1e-5f
#define FEAT  256
#define MAXM  100352   // 100000 rounded up to a multiple of 128

// Scratch (static device allocations — no cudaMalloc allowed)
__device__ float g_z[(size_t)MAXM * FEAT];     // x @ W
__device__ float g_h[(size_t)MAXM * FEAT];     // h_tan
__device__ float g_bhyp[FEAT];                 // exp_0(bias)
__device__ float g_scal[4];                    // c, sqrt_c, ||b_hyp||^2

// ---------------------------------------------------------------------------
// Prep: scalars + b_hyp (one block, 256 threads)
// ---------------------------------------------------------------------------
__global__ void prep_kernel(const float* __restrict__ bias,
                            const float* __restrict__ ctheta) {
    __shared__ float red[256];
    __shared__ float sh_scale;
    int t = threadIdx.x;
    float b = bias[t];
    red[t] = b * b;
    __syncthreads();
    for (int s = 128; s > 0; s >>= 1) {
        if (t < s) red[t] += red[t + s];
        __syncthreads();
    }
    if (t == 0) {
        float bb = red[0];
        float ct = ctheta[0];
        float c  = log1pf(expf(ct));          // softplus
        float sc = sqrtf(c);
        float nb = fmaxf(sqrtf(bb), EPS);
        float arg = sc * nb;
        float s  = tanhf(arg) / arg;          // b_hyp = s * bias
        g_scal[0] = c;
        g_scal[1] = sc;
        g_scal[2] = s * s * bb;               // ||b_hyp||^2
        sh_scale = s;
    }
    __syncthreads();
    g_bhyp[t] = sh_scale * bias[t];
}

// ---------------------------------------------------------------------------
// GEMM: g_z[M,256] = x[M,256] @ W[256,256]   (128x128 tile, BK=16, 8x8/thread)
// ---------------------------------------------------------------------------
__global__ __launch_bounds__(256) void gemm_kernel(const float* __restrict__ A,
                                                   const float* __restrict__ B,
                                                   int M) {
    __shared__ __align__(16) float As[16][128];   // [k][row]
    __shared__ __align__(16) float Bs[16][128];   // [k][col]
    const int tid  = threadIdx.x;
    const int brow = blockIdx.y * 128;
    const int bcol = blockIdx.x * 128;
    const int ty   = tid >> 4;     // 0..15  -> rows ty*8..
    const int tx   = tid & 15;     // 0..15  -> cols tx*8..

    float acc[8][8];
#pragma unroll
    for (int i = 0; i < 8; i++)
#pragma unroll
        for (int j = 0; j < 8; j++) acc[i][j] = 0.0f;

    for (int k0 = 0; k0 < 256; k0 += 16) {
        // A tile: 128 rows x 16 k  (512 float4, 2 per thread), store transposed
#pragma unroll
        for (int i = 0; i < 2; i++) {
            int q  = tid + i * 256;
            int r  = q >> 2;
            int kc = (q & 3) << 2;
            float4 v = make_float4(0.f, 0.f, 0.f, 0.f);
            int grow = brow + r;
            if (grow < M)
                v = *(const float4*)(A + (size_t)grow * 256 + k0 + kc);
            As[kc + 0][r] = v.x;
            As[kc + 1][r] = v.y;
            As[kc + 2][r] = v.z;
            As[kc + 3][r] = v.w;
        }
        // B tile: 16 k x 128 cols (512 float4, 2 per thread)
#pragma unroll
        for (int i = 0; i < 2; i++) {
            int q  = tid + i * 256;
            int kr = q >> 5;
            int cc = (q & 31) << 2;
            *(float4*)&Bs[kr][cc] =
                *(const float4*)(B + (size_t)(k0 + kr) * 256 + bcol + cc);
        }
        __syncthreads();
#pragma unroll
        for (int k = 0; k < 16; k++) {
            float a[8], b[8];
            *(float4*)(a)     = *(const float4*)&As[k][ty * 8];
            *(float4*)(a + 4) = *(const float4*)&As[k][ty * 8 + 4];
            *(float4*)(b)     = *(const float4*)&Bs[k][tx * 8];
            *(float4*)(b + 4) = *(const float4*)&Bs[k][tx * 8 + 4];
#pragma unroll
            for (int i = 0; i < 8; i++)
#pragma unroll
                for (int j = 0; j < 8; j++)
                    acc[i][j] = fmaf(a[i], b[j], acc[i][j]);
        }
        __syncthreads();
    }
#pragma unroll
    for (int i = 0; i < 8; i++) {
        int grow = brow + ty * 8 + i;
        if (grow < M) {
            float* dst = g_z + (size_t)grow * 256 + bcol + tx * 8;
            *(float4*)dst       = *(float4*)&acc[i][0];
            *(float4*)(dst + 4) = *(float4*)&acc[i][4];
        }
    }
}

// ---------------------------------------------------------------------------
// Hyperbolic map: warp per row.
// h_tan = A*z + B*b_hyp with scalars from 2 reductions (||z||^2, <z,b_hyp>)
// ---------------------------------------------------------------------------
__global__ __launch_bounds__(256) void hyp_kernel(int M) {
    int warp = (blockIdx.x * blockDim.x + threadIdx.x) >> 5;
    int lane = threadIdx.x & 31;
    if (warp >= M) return;

    const float c  = g_scal[0];
    const float sc = g_scal[1];
    const float B2 = g_scal[2];   // ||b_hyp||^2

    const float* zr = g_z + (size_t)warp * 256 + lane * 8;
    float4 z0 = *(const float4*)(zr);
    float4 z1 = *(const float4*)(zr + 4);
    float4 b0 = *(const float4*)(g_bhyp + lane * 8);
    float4 b1 = *(const float4*)(g_bhyp + lane * 8 + 4);

    float zz = z0.x*z0.x + z0.y*z0.y + z0.z*z0.z + z0.w*z0.w
             + z1.x*z1.x + z1.y*z1.y + z1.z*z1.z + z1.w*z1.w;
    float zb = z0.x*b0.x + z0.y*b0.y + z0.z*b0.z + z0.w*b0.w
             + z1.x*b1.x + z1.y*b1.y + z1.z*b1.z + z1.w*b1.w;
#pragma unroll
    for (int o = 16; o > 0; o >>= 1) {
        zz += __shfl_xor_sync(0xffffffffu, zz, o);
        zb += __shfl_xor_sync(0xffffffffu, zb, o);
    }

    // exp map of z
    float nz  = fmaxf(sqrtf(zz), EPS);
    float ag  = sc * nz;
    float sz  = tanhf(ag) / ag;          // z_hyp = sz * z
    float aa  = sz * sz * zz;            // ||z_hyp||^2
    float ab  = sz * zb;                 // <z_hyp, b_hyp>

    // mobius add: h = alpha*z_hyp + beta*b_hyp
    float k2  = 1.0f + 2.0f * c * ab + c * B2;
    float k1  = 1.0f - c * aa;
    float den = fmaxf(1.0f + 2.0f * c * ab + c * c * aa * B2, EPS);
    float alpha = k2 / den;
    float beta  = k1 / den;

    // ||h||^2 in closed form
    float hh = alpha * alpha * aa + 2.0f * alpha * beta * ab + beta * beta * B2;
    float nh = fmaxf(sqrtf(hh), EPS);

    // project to ball
    float maxn = (1.0f - EPS) / sc;
    if (nh > maxn) {
        float s = maxn / nh;
        alpha *= s;
        beta  *= s;
        nh = maxn;
    }

    // log map
    float n3   = fmaxf(nh, EPS);
    float arg2 = fminf(sc * n3, 1.0f - EPS);
    float sl   = atanhf(arg2) / (sc * n3);

    float Az = sl * alpha * sz;   // coefficient on raw z
    float Bb = sl * beta;         // coefficient on b_hyp

    float* hr = g_h + (size_t)warp * 256 + lane * 8;
    float4 o0, o1;
    o0.x = Az*z0.x + Bb*b0.x;  o0.y = Az*z0.y + Bb*b0.y;
    o0.z = Az*z0.z + Bb*b0.z;  o0.w = Az*z0.w + Bb*b0.w;
    o1.x = Az*z1.x + Bb*b1.x;  o1.y = Az*z1.y + Bb*b1.y;
    o1.z = Az*z1.z + Bb*b1.z;  o1.w = Az*z1.w + Bb*b1.w;
    *(float4*)(hr)     = o0;
    *(float4*)(hr + 4) = o1;
}

// ---------------------------------------------------------------------------
// Edge aggregation: one warp per edge, 128-col chunk per pass (L2 residency),
// vectorized red.global.add.v4.f32
// ---------------------------------------------------------------------------
__global__ __launch_bounds__(256) void edge_kernel(const int*   __restrict__ rows,
                                                   const int*   __restrict__ cols,
                                                   const float* __restrict__ vals,
                                                   float*       __restrict__ out,
                                                   int E, int chunk) {
    int w = (int)((blockIdx.x * (unsigned)blockDim.x + threadIdx.x) >> 5);
    if (w >= E) return;
    int lane = threadIdx.x & 31;

    int   r = __ldg(rows + w);
    int   cidx = __ldg(cols + w);
    float v = __ldg(vals + w);

    int off = chunk * 128 + lane * 4;
    float4 hv = *(const float4*)(g_h + (size_t)cidx * 256 + off);
    float mx = hv.x * v, my = hv.y * v, mz = hv.z * v, mw = hv.w * v;

    float* dst = out + (size_t)r * 256 + off;
    asm volatile("red.global.add.v4.f32 [%0], {%1, %2, %3, %4};"
                 :: "l"(dst), "f"(mx), "f"(my), "f"(mz), "f"(mw)
                 : "memory");
}

// ---------------------------------------------------------------------------
// In-place ReLU
// ---------------------------------------------------------------------------
__global__ __launch_bounds__(256) void relu_kernel(float* __restrict__ out, int n4) {
    int i = blockIdx.x * blockDim.x + threadIdx.x;
    if (i >= n4) return;
    float4* p = (float4*)out + i;
    float4 v = *p;
    v.x = fmaxf(v.x, 0.f);
    v.y = fmaxf(v.y, 0.f);
    v.z = fmaxf(v.z, 0.f);
    v.w = fmaxf(v.w, 0.f);
    *p = v;
}

// ---------------------------------------------------------------------------
extern "C" void kernel_launch(void* const* d_in, const int* in_sizes, int n_in,
                              void* d_out, int out_size) {
    const float* x     = (const float*)d_in[0];
    const int*   arows = (const int*)  d_in[1];
    const int*   acols = (const int*)  d_in[2];
    const float* avals = (const float*)d_in[3];
    const float* W     = (const float*)d_in[4];
    const float* bias  = (const float*)d_in[5];
    const float* ct    = (const float*)d_in[6];
    float* out = (float*)d_out;

    int M = in_sizes[0] / FEAT;
    int E = in_sizes[1];

    prep_kernel<<<1, 256>>>(bias, ct);

    dim3 ggrid(2, (M + 127) / 128);
    gemm_kernel<<<ggrid, 256>>>(x, W, M);

    hyp_kernel<<<(M + 7) / 8, 256>>>(M);

    cudaMemsetAsync(d_out, 0, (size_t)out_size * sizeof(float));

    int eblocks = (E + 7) / 8;            // 8 warps/block, 1 warp/edge
    edge_kernel<<<eblocks, 256>>>(arows, acols, avals, out, E, 0);
    edge_kernel<<<eblocks, 256>>>(arows, acols, avals, out, E, 1);

    int n4 = out_size / 4;
    relu_kernel<<<(n4 + 255) / 256, 256>>>(out, n4);
}

// round 3
// speedup vs baseline: 1.4751x; 1.4751x over previous
#include <cuda_runtime.h>
#include <math.h>

#define EPS   1e-5f
#define FEAT  256
#define MAXM  100352   // 100000 rounded up
#define MAXE  3200000

// Scratch (static device allocations — no cudaMalloc allowed)
__device__ float g_z[(size_t)MAXM * FEAT];     // x @ W
__device__ float g_h[(size_t)MAXM * FEAT];     // h_tan
__device__ float g_bhyp[FEAT];                 // exp_0(bias)
__device__ float g_scal[4];                    // c, sqrt_c, ||b_hyp||^2
// CSR structures
__device__ int  g_deg[MAXM];
__device__ int  g_off[MAXM + 1];
__device__ int  g_pos[MAXM];
__device__ int2 g_epack[MAXE];                 // (col, val-bits) in CSR order

// ---------------------------------------------------------------------------
// Prep: scalars + b_hyp (one block, 256 threads)
// ---------------------------------------------------------------------------
__global__ void prep_kernel(const float* __restrict__ bias,
                            const float* __restrict__ ctheta) {
    __shared__ float red[256];
    __shared__ float sh_scale;
    int t = threadIdx.x;
    float b = bias[t];
    red[t] = b * b;
    __syncthreads();
    for (int s = 128; s > 0; s >>= 1) {
        if (t < s) red[t] += red[t + s];
        __syncthreads();
    }
    if (t == 0) {
        float bb = red[0];
        float ct = ctheta[0];
        float c  = log1pf(expf(ct));          // softplus
        float sc = sqrtf(c);
        float nb = fmaxf(sqrtf(bb), EPS);
        float arg = sc * nb;
        float s  = tanhf(arg) / arg;          // b_hyp = s * bias
        g_scal[0] = c;
        g_scal[1] = sc;
        g_scal[2] = s * s * bb;               // ||b_hyp||^2
        sh_scale = s;
    }
    __syncthreads();
    g_bhyp[t] = sh_scale * bias[t];
}

// ---------------------------------------------------------------------------
// GEMM: g_z[M,256] = x[M,256] @ W[256,256]   (128x128 tile, BK=16, 8x8/thread)
// ---------------------------------------------------------------------------
__global__ __launch_bounds__(256) void gemm_kernel(const float* __restrict__ A,
                                                   const float* __restrict__ B,
                                                   int M) {
    __shared__ __align__(16) float As[16][128];   // [k][row]
    __shared__ __align__(16) float Bs[16][128];   // [k][col]
    const int tid  = threadIdx.x;
    const int brow = blockIdx.y * 128;
    const int bcol = blockIdx.x * 128;
    const int ty   = tid >> 4;
    const int tx   = tid & 15;

    float acc[8][8];
#pragma unroll
    for (int i = 0; i < 8; i++)
#pragma unroll
        for (int j = 0; j < 8; j++) acc[i][j] = 0.0f;

    for (int k0 = 0; k0 < 256; k0 += 16) {
#pragma unroll
        for (int i = 0; i < 2; i++) {
            int q  = tid + i * 256;
            int r  = q >> 2;
            int kc = (q & 3) << 2;
            float4 v = make_float4(0.f, 0.f, 0.f, 0.f);
            int grow = brow + r;
            if (grow < M)
                v = *(const float4*)(A + (size_t)grow * 256 + k0 + kc);
            As[kc + 0][r] = v.x;
            As[kc + 1][r] = v.y;
            As[kc + 2][r] = v.z;
            As[kc + 3][r] = v.w;
        }
#pragma unroll
        for (int i = 0; i < 2; i++) {
            int q  = tid + i * 256;
            int kr = q >> 5;
            int cc = (q & 31) << 2;
            *(float4*)&Bs[kr][cc] =
                *(const float4*)(B + (size_t)(k0 + kr) * 256 + bcol + cc);
        }
        __syncthreads();
#pragma unroll
        for (int k = 0; k < 16; k++) {
            float a[8], b[8];
            *(float4*)(a)     = *(const float4*)&As[k][ty * 8];
            *(float4*)(a + 4) = *(const float4*)&As[k][ty * 8 + 4];
            *(float4*)(b)     = *(const float4*)&Bs[k][tx * 8];
            *(float4*)(b + 4) = *(const float4*)&Bs[k][tx * 8 + 4];
#pragma unroll
            for (int i = 0; i < 8; i++)
#pragma unroll
                for (int j = 0; j < 8; j++)
                    acc[i][j] = fmaf(a[i], b[j], acc[i][j]);
        }
        __syncthreads();
    }
#pragma unroll
    for (int i = 0; i < 8; i++) {
        int grow = brow + ty * 8 + i;
        if (grow < M) {
            float* dst = g_z + (size_t)grow * 256 + bcol + tx * 8;
            *(float4*)dst       = *(float4*)&acc[i][0];
            *(float4*)(dst + 4) = *(float4*)&acc[i][4];
        }
    }
}

// ---------------------------------------------------------------------------
// Hyperbolic map: warp per row.
// ---------------------------------------------------------------------------
__global__ __launch_bounds__(256) void hyp_kernel(int M) {
    int warp = (blockIdx.x * blockDim.x + threadIdx.x) >> 5;
    int lane = threadIdx.x & 31;
    if (warp >= M) return;

    const float c  = g_scal[0];
    const float sc = g_scal[1];
    const float B2 = g_scal[2];

    const float* zr = g_z + (size_t)warp * 256 + lane * 8;
    float4 z0 = *(const float4*)(zr);
    float4 z1 = *(const float4*)(zr + 4);
    float4 b0 = *(const float4*)(g_bhyp + lane * 8);
    float4 b1 = *(const float4*)(g_bhyp + lane * 8 + 4);

    float zz = z0.x*z0.x + z0.y*z0.y + z0.z*z0.z + z0.w*z0.w
             + z1.x*z1.x + z1.y*z1.y + z1.z*z1.z + z1.w*z1.w;
    float zb = z0.x*b0.x + z0.y*b0.y + z0.z*b0.z + z0.w*b0.w
             + z1.x*b1.x + z1.y*b1.y + z1.z*b1.z + z1.w*b1.w;
#pragma unroll
    for (int o = 16; o > 0; o >>= 1) {
        zz += __shfl_xor_sync(0xffffffffu, zz, o);
        zb += __shfl_xor_sync(0xffffffffu, zb, o);
    }

    float nz  = fmaxf(sqrtf(zz), EPS);
    float ag  = sc * nz;
    float sz  = tanhf(ag) / ag;
    float aa  = sz * sz * zz;
    float ab  = sz * zb;

    float k2  = 1.0f + 2.0f * c * ab + c * B2;
    float k1  = 1.0f - c * aa;
    float den = fmaxf(1.0f + 2.0f * c * ab + c * c * aa * B2, EPS);
    float alpha = k2 / den;
    float beta  = k1 / den;

    float hh = alpha * alpha * aa + 2.0f * alpha * beta * ab + beta * beta * B2;
    float nh = fmaxf(sqrtf(hh), EPS);

    float maxn = (1.0f - EPS) / sc;
    if (nh > maxn) {
        float s = maxn / nh;
        alpha *= s;
        beta  *= s;
        nh = maxn;
    }

    float n3   = fmaxf(nh, EPS);
    float arg2 = fminf(sc * n3, 1.0f - EPS);
    float sl   = atanhf(arg2) / (sc * n3);

    float Az = sl * alpha * sz;
    float Bb = sl * beta;

    float* hr = g_h + (size_t)warp * 256 + lane * 8;
    float4 o0, o1;
    o0.x = Az*z0.x + Bb*b0.x;  o0.y = Az*z0.y + Bb*b0.y;
    o0.z = Az*z0.z + Bb*b0.z;  o0.w = Az*z0.w + Bb*b0.w;
    o1.x = Az*z1.x + Bb*b1.x;  o1.y = Az*z1.y + Bb*b1.y;
    o1.z = Az*z1.z + Bb*b1.z;  o1.w = Az*z1.w + Bb*b1.w;
    *(float4*)(hr)     = o0;
    *(float4*)(hr + 4) = o1;
}

// ---------------------------------------------------------------------------
// CSR build
// ---------------------------------------------------------------------------
__global__ void zero_deg_kernel(int M) {
    int i = blockIdx.x * blockDim.x + threadIdx.x;
    if (i < M) g_deg[i] = 0;
}

__global__ void hist_kernel(const int* __restrict__ rows, int E) {
    int i = blockIdx.x * blockDim.x + threadIdx.x;
    int stride = gridDim.x * blockDim.x;
    for (int e = i; e < E; e += stride)
        atomicAdd(&g_deg[__ldg(rows + e)], 1);
}

// Single-block exclusive scan of g_deg -> g_off (and g_pos copy)
__global__ void scan_kernel(int M) {
    __shared__ int sh[1024];
    const int t  = threadIdx.x;
    const int CH = (M + 1023) / 1024;
    const int b  = t * CH;

    int s = 0;
    for (int i = 0; i < CH; i++) {
        int idx = b + i;
        if (idx < M) s += g_deg[idx];
    }
    sh[t] = s;
    __syncthreads();
    // Hillis-Steele inclusive scan over 1024
    for (int off = 1; off < 1024; off <<= 1) {
        int v = (t >= off) ? sh[t - off] : 0;
        __syncthreads();
        sh[t] += v;
        __syncthreads();
    }
    int run = (t == 0) ? 0 : sh[t - 1];
    for (int i = 0; i < CH; i++) {
        int idx = b + i;
        if (idx < M) {
            g_off[idx] = run;
            g_pos[idx] = run;
            run += g_deg[idx];
        }
    }
    if (t == 1023) g_off[M] = run;
}

__global__ void scatter_kernel(const int*   __restrict__ rows,
                               const int*   __restrict__ cols,
                               const float* __restrict__ vals, int E) {
    int i = blockIdx.x * blockDim.x + threadIdx.x;
    int stride = gridDim.x * blockDim.x;
    for (int e = i; e < E; e += stride) {
        int r = __ldg(rows + e);
        int p = atomicAdd(&g_pos[r], 1);
        g_epack[p] = make_int2(__ldg(cols + e), __float_as_int(__ldg(vals + e)));
    }
}

// ---------------------------------------------------------------------------
// Row aggregation: warp per row, 128-col chunk, fused ReLU, single write.
// 4-deep unroll for gather MLP.
// ---------------------------------------------------------------------------
__global__ __launch_bounds__(256) void row_kernel(float* __restrict__ out,
                                                  int M, int chunk) {
    int row = (int)((blockIdx.x * (unsigned)blockDim.x + threadIdx.x) >> 5);
    if (row >= M) return;
    int lane = threadIdx.x & 31;

    int beg = __ldg(g_off + row);
    int end = __ldg(g_off + row + 1);
    const int off = chunk * 128 + lane * 4;

    float ax = 0.f, ay = 0.f, az = 0.f, aw = 0.f;

    int e = beg;
    for (; e + 3 < end; e += 4) {
        int2 p0 = __ldg(g_epack + e);
        int2 p1 = __ldg(g_epack + e + 1);
        int2 p2 = __ldg(g_epack + e + 2);
        int2 p3 = __ldg(g_epack + e + 3);
        float4 h0 = *(const float4*)(g_h + (size_t)p0.x * FEAT + off);
        float4 h1 = *(const float4*)(g_h + (size_t)p1.x * FEAT + off);
        float4 h2 = *(const float4*)(g_h + (size_t)p2.x * FEAT + off);
        float4 h3 = *(const float4*)(g_h + (size_t)p3.x * FEAT + off);
        float v0 = __int_as_float(p0.y);
        float v1 = __int_as_float(p1.y);
        float v2 = __int_as_float(p2.y);
        float v3 = __int_as_float(p3.y);
        ax = fmaf(v0, h0.x, ax); ay = fmaf(v0, h0.y, ay);
        az = fmaf(v0, h0.z, az); aw = fmaf(v0, h0.w, aw);
        ax = fmaf(v1, h1.x, ax); ay = fmaf(v1, h1.y, ay);
        az = fmaf(v1, h1.z, az); aw = fmaf(v1, h1.w, aw);
        ax = fmaf(v2, h2.x, ax); ay = fmaf(v2, h2.y, ay);
        az = fmaf(v2, h2.z, az); aw = fmaf(v2, h2.w, aw);
        ax = fmaf(v3, h3.x, ax); ay = fmaf(v3, h3.y, ay);
        az = fmaf(v3, h3.z, az); aw = fmaf(v3, h3.w, aw);
    }
    for (; e < end; e++) {
        int2 p0 = __ldg(g_epack + e);
        float v0 = __int_as_float(p0.y);
        float4 h0 = *(const float4*)(g_h + (size_t)p0.x * FEAT + off);
        ax = fmaf(v0, h0.x, ax); ay = fmaf(v0, h0.y, ay);
        az = fmaf(v0, h0.z, az); aw = fmaf(v0, h0.w, aw);
    }

    float4 o;
    o.x = fmaxf(ax, 0.f);
    o.y = fmaxf(ay, 0.f);
    o.z = fmaxf(az, 0.f);
    o.w = fmaxf(aw, 0.f);
    *(float4*)(out + (size_t)row * FEAT + off) = o;
}

// ---------------------------------------------------------------------------
extern "C" void kernel_launch(void* const* d_in, const int* in_sizes, int n_in,
                              void* d_out, int out_size) {
    const float* x     = (const float*)d_in[0];
    const int*   arows = (const int*)  d_in[1];
    const int*   acols = (const int*)  d_in[2];
    const float* avals = (const float*)d_in[3];
    const float* W     = (const float*)d_in[4];
    const float* bias  = (const float*)d_in[5];
    const float* ct    = (const float*)d_in[6];
    float* out = (float*)d_out;

    int M = in_sizes[0] / FEAT;
    int E = in_sizes[1];

    prep_kernel<<<1, 256>>>(bias, ct);

    // CSR build (independent of GEMM result)
    zero_deg_kernel<<<(M + 255) / 256, 256>>>(M);
    hist_kernel<<<592, 256>>>(arows, E);         // grid-stride, ~4 SM waves
    scan_kernel<<<1, 1024>>>(M);
    scatter_kernel<<<592, 256>>>(arows, acols, avals, E);

    dim3 ggrid(2, (M + 127) / 128);
    gemm_kernel<<<ggrid, 256>>>(x, W, M);

    hyp_kernel<<<(M + 7) / 8, 256>>>(M);

    int rblocks = (M + 7) / 8;                   // 8 warps/block, 1 warp/row
    row_kernel<<<rblocks, 256>>>(out, M, 0);
    row_kernel<<<rblocks, 256>>>(out, M, 1);
}

// round 4
// speedup vs baseline: 1.8245x; 1.2369x over previous
#include <cuda_runtime.h>
#include <math.h>

#define EPS   1e-5f
#define FEAT  256
#define MAXM  100352   // 100000 rounded up
#define MAXE  3200000
#define NBMAX 128      // max scan blocks (ceil(MAXM/1024)=98)

// Scratch (static device allocations — no cudaMalloc allowed)
__device__ float g_z[(size_t)MAXM * FEAT];     // x @ W
__device__ float g_h[(size_t)MAXM * FEAT];     // h_tan
__device__ float g_bhyp[FEAT];                 // exp_0(bias)
__device__ float g_scal[4];                    // c, sqrt_c, ||b_hyp||^2
// CSR structures
__device__ int  g_deg[MAXM];
__device__ int  g_off[MAXM + 1];
__device__ int  g_pos[MAXM];
__device__ int  g_bsum[NBMAX];
__device__ int  g_boff[NBMAX];
__device__ int2 g_epack[MAXE];                 // (col, val-bits) in CSR order

// ---------------------------------------------------------------------------
// Prep: scalars + b_hyp (one block, 256 threads)
// ---------------------------------------------------------------------------
__global__ void prep_kernel(const float* __restrict__ bias,
                            const float* __restrict__ ctheta) {
    __shared__ float red[256];
    __shared__ float sh_scale;
    int t = threadIdx.x;
    float b = bias[t];
    red[t] = b * b;
    __syncthreads();
    for (int s = 128; s > 0; s >>= 1) {
        if (t < s) red[t] += red[t + s];
        __syncthreads();
    }
    if (t == 0) {
        float bb = red[0];
        float ct = ctheta[0];
        float c  = log1pf(expf(ct));          // softplus
        float sc = sqrtf(c);
        float nb = fmaxf(sqrtf(bb), EPS);
        float arg = sc * nb;
        float s  = tanhf(arg) / arg;          // b_hyp = s * bias
        g_scal[0] = c;
        g_scal[1] = sc;
        g_scal[2] = s * s * bb;               // ||b_hyp||^2
        sh_scale = s;
    }
    __syncthreads();
    g_bhyp[t] = sh_scale * bias[t];
}

// ---------------------------------------------------------------------------
// GEMM: g_z[M,256] = x[M,256] @ W[256,256]   (128x128 tile, BK=16, 8x8/thread)
// ---------------------------------------------------------------------------
__global__ __launch_bounds__(256) void gemm_kernel(const float* __restrict__ A,
                                                   const float* __restrict__ B,
                                                   int M) {
    __shared__ __align__(16) float As[16][128];   // [k][row]
    __shared__ __align__(16) float Bs[16][128];   // [k][col]
    const int tid  = threadIdx.x;
    const int brow = blockIdx.y * 128;
    const int bcol = blockIdx.x * 128;
    const int ty   = tid >> 4;
    const int tx   = tid & 15;

    float acc[8][8];
#pragma unroll
    for (int i = 0; i < 8; i++)
#pragma unroll
        for (int j = 0; j < 8; j++) acc[i][j] = 0.0f;

    for (int k0 = 0; k0 < 256; k0 += 16) {
#pragma unroll
        for (int i = 0; i < 2; i++) {
            int q  = tid + i * 256;
            int r  = q >> 2;
            int kc = (q & 3) << 2;
            float4 v = make_float4(0.f, 0.f, 0.f, 0.f);
            int grow = brow + r;
            if (grow < M)
                v = *(const float4*)(A + (size_t)grow * 256 + k0 + kc);
            As[kc + 0][r] = v.x;
            As[kc + 1][r] = v.y;
            As[kc + 2][r] = v.z;
            As[kc + 3][r] = v.w;
        }
#pragma unroll
        for (int i = 0; i < 2; i++) {
            int q  = tid + i * 256;
            int kr = q >> 5;
            int cc = (q & 31) << 2;
            *(float4*)&Bs[kr][cc] =
                *(const float4*)(B + (size_t)(k0 + kr) * 256 + bcol + cc);
        }
        __syncthreads();
#pragma unroll
        for (int k = 0; k < 16; k++) {
            float a[8], b[8];
            *(float4*)(a)     = *(const float4*)&As[k][ty * 8];
            *(float4*)(a + 4) = *(const float4*)&As[k][ty * 8 + 4];
            *(float4*)(b)     = *(const float4*)&Bs[k][tx * 8];
            *(float4*)(b + 4) = *(const float4*)&Bs[k][tx * 8 + 4];
#pragma unroll
            for (int i = 0; i < 8; i++)
#pragma unroll
                for (int j = 0; j < 8; j++)
                    acc[i][j] = fmaf(a[i], b[j], acc[i][j]);
        }
        __syncthreads();
    }
#pragma unroll
    for (int i = 0; i < 8; i++) {
        int grow = brow + ty * 8 + i;
        if (grow < M) {
            float* dst = g_z + (size_t)grow * 256 + bcol + tx * 8;
            *(float4*)dst       = *(float4*)&acc[i][0];
            *(float4*)(dst + 4) = *(float4*)&acc[i][4];
        }
    }
}

// ---------------------------------------------------------------------------
// Hyperbolic map: warp per row.
// ---------------------------------------------------------------------------
__global__ __launch_bounds__(256) void hyp_kernel(int M) {
    int warp = (blockIdx.x * blockDim.x + threadIdx.x) >> 5;
    int lane = threadIdx.x & 31;
    if (warp >= M) return;

    const float c  = g_scal[0];
    const float sc = g_scal[1];
    const float B2 = g_scal[2];

    const float* zr = g_z + (size_t)warp * 256 + lane * 8;
    float4 z0 = *(const float4*)(zr);
    float4 z1 = *(const float4*)(zr + 4);
    float4 b0 = *(const float4*)(g_bhyp + lane * 8);
    float4 b1 = *(const float4*)(g_bhyp + lane * 8 + 4);

    float zz = z0.x*z0.x + z0.y*z0.y + z0.z*z0.z + z0.w*z0.w
             + z1.x*z1.x + z1.y*z1.y + z1.z*z1.z + z1.w*z1.w;
    float zb = z0.x*b0.x + z0.y*b0.y + z0.z*b0.z + z0.w*b0.w
             + z1.x*b1.x + z1.y*b1.y + z1.z*b1.z + z1.w*b1.w;
#pragma unroll
    for (int o = 16; o > 0; o >>= 1) {
        zz += __shfl_xor_sync(0xffffffffu, zz, o);
        zb += __shfl_xor_sync(0xffffffffu, zb, o);
    }

    float nz  = fmaxf(sqrtf(zz), EPS);
    float ag  = sc * nz;
    float sz  = tanhf(ag) / ag;
    float aa  = sz * sz * zz;
    float ab  = sz * zb;

    float k2  = 1.0f + 2.0f * c * ab + c * B2;
    float k1  = 1.0f - c * aa;
    float den = fmaxf(1.0f + 2.0f * c * ab + c * c * aa * B2, EPS);
    float alpha = k2 / den;
    float beta  = k1 / den;

    float hh = alpha * alpha * aa + 2.0f * alpha * beta * ab + beta * beta * B2;
    float nh = fmaxf(sqrtf(hh), EPS);

    float maxn = (1.0f - EPS) / sc;
    if (nh > maxn) {
        float s = maxn / nh;
        alpha *= s;
        beta  *= s;
        nh = maxn;
    }

    float n3   = fmaxf(nh, EPS);
    float arg2 = fminf(sc * n3, 1.0f - EPS);
    float sl   = atanhf(arg2) / (sc * n3);

    float Az = sl * alpha * sz;
    float Bb = sl * beta;

    float* hr = g_h + (size_t)warp * 256 + lane * 8;
    float4 o0, o1;
    o0.x = Az*z0.x + Bb*b0.x;  o0.y = Az*z0.y + Bb*b0.y;
    o0.z = Az*z0.z + Bb*b0.z;  o0.w = Az*z0.w + Bb*b0.w;
    o1.x = Az*z1.x + Bb*b1.x;  o1.y = Az*z1.y + Bb*b1.y;
    o1.z = Az*z1.z + Bb*b1.z;  o1.w = Az*z1.w + Bb*b1.w;
    *(float4*)(hr)     = o0;
    *(float4*)(hr + 4) = o1;
}

// ---------------------------------------------------------------------------
// CSR build
// ---------------------------------------------------------------------------
__global__ void zero_deg_kernel(int M) {
    int i = blockIdx.x * blockDim.x + threadIdx.x;
    if (i < M) g_deg[i] = 0;
}

__global__ void hist_kernel(const int* __restrict__ rows, int E) {
    int i = blockIdx.x * blockDim.x + threadIdx.x;
    int stride = gridDim.x * blockDim.x;
    for (int e = i; e < E; e += stride)
        atomicAdd(&g_deg[__ldg(rows + e)], 1);
}

// Pass 1: per-block sums of g_deg (1024 elems per block)
__global__ __launch_bounds__(1024) void scan1_kernel(int M) {
    __shared__ int sh[32];
    int t   = threadIdx.x;
    int idx = blockIdx.x * 1024 + t;
    int v   = (idx < M) ? g_deg[idx] : 0;
#pragma unroll
    for (int o = 16; o > 0; o >>= 1)
        v += __shfl_down_sync(0xffffffffu, v, o);
    if ((t & 31) == 0) sh[t >> 5] = v;
    __syncthreads();
    if (t < 32) {
        int s = sh[t];
#pragma unroll
        for (int o = 16; o > 0; o >>= 1)
            s += __shfl_down_sync(0xffffffffu, s, o);
        if (t == 0) g_bsum[blockIdx.x] = s;
    }
}

// Pass 2: exclusive scan of nb (<=128) block sums; also write g_off[M] = E
__global__ void scan2_kernel(int nb, int M, int E) {
    __shared__ int sh[NBMAX];
    int t = threadIdx.x;
    int v = (t < nb) ? g_bsum[t] : 0;
    sh[t] = v;
    __syncthreads();
    for (int o = 1; o < NBMAX; o <<= 1) {
        int u = (t >= o) ? sh[t - o] : 0;
        __syncthreads();
        sh[t] += u;
        __syncthreads();
    }
    if (t < nb) g_boff[t] = sh[t] - v;   // exclusive
    if (t == 0) g_off[M] = E;
}

// Pass 3: per-block exclusive scan + block offset -> g_off, g_pos
__global__ __launch_bounds__(1024) void scan3_kernel(int M) {
    __shared__ int sh[1024];
    int t   = threadIdx.x;
    int idx = blockIdx.x * 1024 + t;
    int v   = (idx < M) ? g_deg[idx] : 0;
    sh[t] = v;
    __syncthreads();
    for (int o = 1; o < 1024; o <<= 1) {
        int u = (t >= o) ? sh[t - o] : 0;
        __syncthreads();
        sh[t] += u;
        __syncthreads();
    }
    if (idx < M) {
        int off = g_boff[blockIdx.x] + sh[t] - v;   // exclusive
        g_off[idx] = off;
        g_pos[idx] = off;
    }
}

__global__ void scatter_kernel(const int*   __restrict__ rows,
                               const int*   __restrict__ cols,
                               const float* __restrict__ vals, int E) {
    int i = blockIdx.x * blockDim.x + threadIdx.x;
    int stride = gridDim.x * blockDim.x;
    for (int e = i; e < E; e += stride) {
        int r = __ldg(rows + e);
        int p = atomicAdd(&g_pos[r], 1);
        g_epack[p] = make_int2(__ldg(cols + e), __float_as_int(__ldg(vals + e)));
    }
}

// ---------------------------------------------------------------------------
// Row aggregation: warp per row, 128-col chunk, fused ReLU, single write.
// 4-deep unroll for gather MLP.
// ---------------------------------------------------------------------------
__global__ __launch_bounds__(256) void row_kernel(float* __restrict__ out,
                                                  int M, int chunk) {
    int row = (int)((blockIdx.x * (unsigned)blockDim.x + threadIdx.x) >> 5);
    if (row >= M) return;
    int lane = threadIdx.x & 31;

    int beg = __ldg(g_off + row);
    int end = __ldg(g_off + row + 1);
    const int off = chunk * 128 + lane * 4;

    float ax = 0.f, ay = 0.f, az = 0.f, aw = 0.f;

    int e = beg;
    for (; e + 3 < end; e += 4) {
        int2 p0 = __ldg(g_epack + e);
        int2 p1 = __ldg(g_epack + e + 1);
        int2 p2 = __ldg(g_epack + e + 2);
        int2 p3 = __ldg(g_epack + e + 3);
        float4 h0 = *(const float4*)(g_h + (size_t)p0.x * FEAT + off);
        float4 h1 = *(const float4*)(g_h + (size_t)p1.x * FEAT + off);
        float4 h2 = *(const float4*)(g_h + (size_t)p2.x * FEAT + off);
        float4 h3 = *(const float4*)(g_h + (size_t)p3.x * FEAT + off);
        float v0 = __int_as_float(p0.y);
        float v1 = __int_as_float(p1.y);
        float v2 = __int_as_float(p2.y);
        float v3 = __int_as_float(p3.y);
        ax = fmaf(v0, h0.x, ax); ay = fmaf(v0, h0.y, ay);
        az = fmaf(v0, h0.z, az); aw = fmaf(v0, h0.w, aw);
        ax = fmaf(v1, h1.x, ax); ay = fmaf(v1, h1.y, ay);
        az = fmaf(v1, h1.z, az); aw = fmaf(v1, h1.w, aw);
        ax = fmaf(v2, h2.x, ax); ay = fmaf(v2, h2.y, ay);
        az = fmaf(v2, h2.z, az); aw = fmaf(v2, h2.w, aw);
        ax = fmaf(v3, h3.x, ax); ay = fmaf(v3, h3.y, ay);
        az = fmaf(v3, h3.z, az); aw = fmaf(v3, h3.w, aw);
    }
    for (; e < end; e++) {
        int2 p0 = __ldg(g_epack + e);
        float v0 = __int_as_float(p0.y);
        float4 h0 = *(const float4*)(g_h + (size_t)p0.x * FEAT + off);
        ax = fmaf(v0, h0.x, ax); ay = fmaf(v0, h0.y, ay);
        az = fmaf(v0, h0.z, az); aw = fmaf(v0, h0.w, aw);
    }

    float4 o;
    o.x = fmaxf(ax, 0.f);
    o.y = fmaxf(ay, 0.f);
    o.z = fmaxf(az, 0.f);
    o.w = fmaxf(aw, 0.f);
    *(float4*)(out + (size_t)row * FEAT + off) = o;
}

// ---------------------------------------------------------------------------
extern "C" void kernel_launch(void* const* d_in, const int* in_sizes, int n_in,
                              void* d_out, int out_size) {
    const float* x     = (const float*)d_in[0];
    const int*   arows = (const int*)  d_in[1];
    const int*   acols = (const int*)  d_in[2];
    const float* avals = (const float*)d_in[3];
    const float* W     = (const float*)d_in[4];
    const float* bias  = (const float*)d_in[5];
    const float* ct    = (const float*)d_in[6];
    float* out = (float*)d_out;

    int M = in_sizes[0] / FEAT;
    int E = in_sizes[1];
    int nb = (M + 1023) / 1024;   // <= 98 for M=100000

    prep_kernel<<<1, 256>>>(bias, ct);

    // CSR build (independent of GEMM result)
    zero_deg_kernel<<<(M + 255) / 256, 256>>>(M);
    hist_kernel<<<592, 256>>>(arows, E);
    scan1_kernel<<<nb, 1024>>>(M);
    scan2_kernel<<<1, NBMAX>>>(nb, M, E);
    scan3_kernel<<<nb, 1024>>>(M);
    scatter_kernel<<<592, 256>>>(arows, acols, avals, E);

    dim3 ggrid(2, (M + 127) / 128);
    gemm_kernel<<<ggrid, 256>>>(x, W, M);

    hyp_kernel<<<(M + 7) / 8, 256>>>(M);

    int rblocks = (M + 7) / 8;                   // 8 warps/block, 1 warp/row
    row_kernel<<<rblocks, 256>>>(out, M, 0);
    row_kernel<<<rblocks, 256>>>(out, M, 1);
}

// round 6
// speedup vs baseline: 1.9244x; 1.0548x over previous
#include <cuda_runtime.h>
#include <math.h>

#define EPS   1e-5f
#define FEAT  256
#define MAXM  100352   // 100000 rounded up
#define MAXE  3200000
#define NBMAX 128      // max scan blocks (ceil(MAXM/1024)=98)

// Scratch (static device allocations — no cudaMalloc allowed)
__device__ float g_z[(size_t)MAXM * FEAT];     // x @ W
__device__ float g_h[(size_t)MAXM * FEAT];     // h_tan
__device__ float g_bhyp[FEAT];                 // exp_0(bias)
__device__ float g_scal[4];                    // c, sqrt_c, ||b_hyp||^2
// CSR structures
__device__ int  g_deg[MAXM];
__device__ int  g_off[MAXM + 1];
__device__ int  g_pos[MAXM];
__device__ int  g_bsum[NBMAX];
__device__ int  g_boff[NBMAX];
__device__ int2 g_epack[MAXE];                 // (col, val-bits) in CSR order

// ---------------------------------------------------------------------------
// f32x2 packed helpers (Blackwell FFMA2 — only reachable via PTX)
// ---------------------------------------------------------------------------
static __device__ __forceinline__ unsigned long long pack2(float lo, float hi) {
    unsigned long long v;
    asm("mov.b64 %0, {%1, %2};" : "=l"(v) : "f"(lo), "f"(hi));
    return v;
}
static __device__ __forceinline__ float2 unpack2(unsigned long long v) {
    float2 r;
    asm("mov.b64 {%0, %1}, %2;" : "=f"(r.x), "=f"(r.y) : "l"(v));
    return r;
}
static __device__ __forceinline__ void fma2(unsigned long long& d,
                                            unsigned long long a,
                                            unsigned long long b) {
    asm("fma.rn.f32x2 %0, %1, %2, %0;" : "+l"(d) : "l"(a), "l"(b));
}

// ---------------------------------------------------------------------------
// Prep: scalars + b_hyp (one block, 256 threads)
// ---------------------------------------------------------------------------
__global__ void prep_kernel(const float* __restrict__ bias,
                            const float* __restrict__ ctheta) {
    __shared__ float red[256];
    __shared__ float sh_scale;
    int t = threadIdx.x;
    float b = bias[t];
    red[t] = b * b;
    __syncthreads();
    for (int s = 128; s > 0; s >>= 1) {
        if (t < s) red[t] += red[t + s];
        __syncthreads();
    }
    if (t == 0) {
        float bb = red[0];
        float ct = ctheta[0];
        float c  = log1pf(expf(ct));          // softplus
        float sc = sqrtf(c);
        float nb = fmaxf(sqrtf(bb), EPS);
        float arg = sc * nb;
        float s  = tanhf(arg) / arg;          // b_hyp = s * bias
        g_scal[0] = c;
        g_scal[1] = sc;
        g_scal[2] = s * s * bb;               // ||b_hyp||^2
        sh_scale = s;
    }
    __syncthreads();
    g_bhyp[t] = sh_scale * bias[t];
}

// ---------------------------------------------------------------------------
// GEMM: g_z[M,256] = x[M,256] @ W[256,256]
// 128x128 tile, BK=16, 8x8/thread, packed f32x2 accumulation
// ---------------------------------------------------------------------------
__global__ __launch_bounds__(256) void gemm_kernel(const float* __restrict__ A,
                                                   const float* __restrict__ B,
                                                   int M) {
    __shared__ __align__(16) float As[16][128];   // [k][row]
    __shared__ __align__(16) float Bs[16][128];   // [k][col]
    const int tid  = threadIdx.x;
    const int brow = blockIdx.y * 128;
    const int bcol = blockIdx.x * 128;
    const int ty   = tid >> 4;
    const int tx   = tid & 15;

    unsigned long long acc2[8][4];
#pragma unroll
    for (int i = 0; i < 8; i++)
#pragma unroll
        for (int j = 0; j < 4; j++) acc2[i][j] = 0ull;

    for (int k0 = 0; k0 < 256; k0 += 16) {
#pragma unroll
        for (int i = 0; i < 2; i++) {
            int q  = tid + i * 256;
            int r  = q >> 2;
            int kc = (q & 3) << 2;
            float4 v = make_float4(0.f, 0.f, 0.f, 0.f);
            int grow = brow + r;
            if (grow < M)
                v = *(const float4*)(A + (size_t)grow * 256 + k0 + kc);
            As[kc + 0][r] = v.x;
            As[kc + 1][r] = v.y;
            As[kc + 2][r] = v.z;
            As[kc + 3][r] = v.w;
        }
#pragma unroll
        for (int i = 0; i < 2; i++) {
            int q  = tid + i * 256;
            int kr = q >> 5;
            int cc = (q & 31) << 2;
            *(float4*)&Bs[kr][cc] =
                *(const float4*)(B + (size_t)(k0 + kr) * 256 + bcol + cc);
        }
        __syncthreads();
#pragma unroll
        for (int k = 0; k < 16; k++) {
            float a[8], b[8];
            *(float4*)(a)     = *(const float4*)&As[k][ty * 8];
            *(float4*)(a + 4) = *(const float4*)&As[k][ty * 8 + 4];
            *(float4*)(b)     = *(const float4*)&Bs[k][tx * 8];
            *(float4*)(b + 4) = *(const float4*)&Bs[k][tx * 8 + 4];

            unsigned long long b2[4], a2[8];
#pragma unroll
            for (int j = 0; j < 4; j++) b2[j] = pack2(b[2 * j], b[2 * j + 1]);
#pragma unroll
            for (int i = 0; i < 8; i++) a2[i] = pack2(a[i], a[i]);
#pragma unroll
            for (int i = 0; i < 8; i++)
#pragma unroll
                for (int j = 0; j < 4; j++)
                    fma2(acc2[i][j], a2[i], b2[j]);
        }
        __syncthreads();
    }
#pragma unroll
    for (int i = 0; i < 8; i++) {
        int grow = brow + ty * 8 + i;
        if (grow < M) {
            float2 p0 = unpack2(acc2[i][0]);
            float2 p1 = unpack2(acc2[i][1]);
            float2 p2 = unpack2(acc2[i][2]);
            float2 p3 = unpack2(acc2[i][3]);
            float* dst = g_z + (size_t)grow * 256 + bcol + tx * 8;
            float4 o0 = make_float4(p0.x, p0.y, p1.x, p1.y);
            float4 o1 = make_float4(p2.x, p2.y, p3.x, p3.y);
            *(float4*)dst       = o0;
            *(float4*)(dst + 4) = o1;
        }
    }
}

// ---------------------------------------------------------------------------
// Hyperbolic map: warp per row.
// ---------------------------------------------------------------------------
__global__ __launch_bounds__(256) void hyp_kernel(int M) {
    int warp = (blockIdx.x * blockDim.x + threadIdx.x) >> 5;
    int lane = threadIdx.x & 31;
    if (warp >= M) return;

    const float c  = g_scal[0];
    const float sc = g_scal[1];
    const float B2 = g_scal[2];

    const float* zr = g_z + (size_t)warp * 256 + lane * 8;
    float4 z0 = *(const float4*)(zr);
    float4 z1 = *(const float4*)(zr + 4);
    float4 b0 = *(const float4*)(g_bhyp + lane * 8);
    float4 b1 = *(const float4*)(g_bhyp + lane * 8 + 4);

    float zz = z0.x*z0.x + z0.y*z0.y + z0.z*z0.z + z0.w*z0.w
             + z1.x*z1.x + z1.y*z1.y + z1.z*z1.z + z1.w*z1.w;
    float zb = z0.x*b0.x + z0.y*b0.y + z0.z*b0.z + z0.w*b0.w
             + z1.x*b1.x + z1.y*b1.y + z1.z*b1.z + z1.w*b1.w;
#pragma unroll
    for (int o = 16; o > 0; o >>= 1) {
        zz += __shfl_xor_sync(0xffffffffu, zz, o);
        zb += __shfl_xor_sync(0xffffffffu, zb, o);
    }

    float nz  = fmaxf(sqrtf(zz), EPS);
    float ag  = sc * nz;
    float sz  = tanhf(ag) / ag;
    float aa  = sz * sz * zz;
    float ab  = sz * zb;

    float k2  = 1.0f + 2.0f * c * ab + c * B2;
    float k1  = 1.0f - c * aa;
    float den = fmaxf(1.0f + 2.0f * c * ab + c * c * aa * B2, EPS);
    float alpha = k2 / den;
    float beta  = k1 / den;

    float hh = alpha * alpha * aa + 2.0f * alpha * beta * ab + beta * beta * B2;
    float nh = fmaxf(sqrtf(hh), EPS);

    float maxn = (1.0f - EPS) / sc;
    if (nh > maxn) {
        float s = maxn / nh;
        alpha *= s;
        beta  *= s;
        nh = maxn;
    }

    float n3   = fmaxf(nh, EPS);
    float arg2 = fminf(sc * n3, 1.0f - EPS);
    float sl   = atanhf(arg2) / (sc * n3);

    float Az = sl * alpha * sz;
    float Bb = sl * beta;

    float* hr = g_h + (size_t)warp * 256 + lane * 8;
    float4 o0, o1;
    o0.x = Az*z0.x + Bb*b0.x;  o0.y = Az*z0.y + Bb*b0.y;
    o0.z = Az*z0.z + Bb*b0.z;  o0.w = Az*z0.w + Bb*b0.w;
    o1.x = Az*z1.x + Bb*b1.x;  o1.y = Az*z1.y + Bb*b1.y;
    o1.z = Az*z1.z + Bb*b1.z;  o1.w = Az*z1.w + Bb*b1.w;
    *(float4*)(hr)     = o0;
    *(float4*)(hr + 4) = o1;
}

// ---------------------------------------------------------------------------
// CSR build
// ---------------------------------------------------------------------------
__global__ void zero_deg_kernel(int M) {
    int i = blockIdx.x * blockDim.x + threadIdx.x;
    if (i < M) g_deg[i] = 0;
}

__global__ void hist_kernel(const int* __restrict__ rows, int E) {
    int i = blockIdx.x * blockDim.x + threadIdx.x;
    int stride = gridDim.x * blockDim.x;
    for (int e = i; e < E; e += stride)
        atomicAdd(&g_deg[__ldg(rows + e)], 1);
}

// Pass 1: per-block sums of g_deg (1024 elems per block)
__global__ __launch_bounds__(1024) void scan1_kernel(int M) {
    __shared__ int sh[32];
    int t   = threadIdx.x;
    int idx = blockIdx.x * 1024 + t;
    int v   = (idx < M) ? g_deg[idx] : 0;
#pragma unroll
    for (int o = 16; o > 0; o >>= 1)
        v += __shfl_down_sync(0xffffffffu, v, o);
    if ((t & 31) == 0) sh[t >> 5] = v;
    __syncthreads();
    if (t < 32) {
        int s = sh[t];
#pragma unroll
        for (int o = 16; o > 0; o >>= 1)
            s += __shfl_down_sync(0xffffffffu, s, o);
        if (t == 0) g_bsum[blockIdx.x] = s;
    }
}

// Pass 2: exclusive scan of nb (<=128) block sums; also write g_off[M] = E
__global__ void scan2_kernel(int nb, int M, int E) {
    __shared__ int sh[NBMAX];
    int t = threadIdx.x;
    int v = (t < nb) ? g_bsum[t] : 0;
    sh[t] = v;
    __syncthreads();
    for (int o = 1; o < NBMAX; o <<= 1) {
        int u = (t >= o) ? sh[t - o] : 0;
        __syncthreads();
        sh[t] += u;
        __syncthreads();
    }
    if (t < nb) g_boff[t] = sh[t] - v;   // exclusive
    if (t == 0) g_off[M] = E;
}

// Pass 3: per-block exclusive scan + block offset -> g_off, g_pos
__global__ __launch_bounds__(1024) void scan3_kernel(int M) {
    __shared__ int sh[1024];
    int t   = threadIdx.x;
    int idx = blockIdx.x * 1024 + t;
    int v   = (idx < M) ? g_deg[idx] : 0;
    sh[t] = v;
    __syncthreads();
    for (int o = 1; o < 1024; o <<= 1) {
        int u = (t >= o) ? sh[t - o] : 0;
        __syncthreads();
        sh[t] += u;
        __syncthreads();
    }
    if (idx < M) {
        int off = g_boff[blockIdx.x] + sh[t] - v;   // exclusive
        g_off[idx] = off;
        g_pos[idx] = off;
    }
}

__global__ void scatter_kernel(const int*   __restrict__ rows,
                               const int*   __restrict__ cols,
                               const float* __restrict__ vals, int E) {
    int i = blockIdx.x * blockDim.x + threadIdx.x;
    int stride = gridDim.x * blockDim.x;
    for (int e = i; e < E; e += stride) {
        int r = __ldg(rows + e);
        int p = atomicAdd(&g_pos[r], 1);
        g_epack[p] = make_int2(__ldg(cols + e), __float_as_int(__ldg(vals + e)));
    }
}

// ---------------------------------------------------------------------------
// Row aggregation: warp per row, 128-col chunk, fused ReLU, single write.
// 4-deep unroll for gather MLP.
// ---------------------------------------------------------------------------
__global__ __launch_bounds__(256) void row_kernel(float* __restrict__ out,
                                                  int M, int chunk) {
    int row = (int)((blockIdx.x * (unsigned)blockDim.x + threadIdx.x) >> 5);
    if (row >= M) return;
    int lane = threadIdx.x & 31;

    int beg = __ldg(g_off + row);
    int end = __ldg(g_off + row + 1);
    const int off = chunk * 128 + lane * 4;

    float ax = 0.f, ay = 0.f, az = 0.f, aw = 0.f;

    int e = beg;
    for (; e + 3 < end; e += 4) {
        int2 p0 = __ldg(g_epack + e);
        int2 p1 = __ldg(g_epack + e + 1);
        int2 p2 = __ldg(g_epack + e + 2);
        int2 p3 = __ldg(g_epack + e + 3);
        float4 h0 = *(const float4*)(g_h + (size_t)p0.x * FEAT + off);
        float4 h1 = *(const float4*)(g_h + (size_t)p1.x * FEAT + off);
        float4 h2 = *(const float4*)(g_h + (size_t)p2.x * FEAT + off);
        float4 h3 = *(const float4*)(g_h + (size_t)p3.x * FEAT + off);
        float v0 = __int_as_float(p0.y);
        float v1 = __int_as_float(p1.y);
        float v2 = __int_as_float(p2.y);
        float v3 = __int_as_float(p3.y);
        ax = fmaf(v0, h0.x, ax); ay = fmaf(v0, h0.y, ay);
        az = fmaf(v0, h0.z, az); aw = fmaf(v0, h0.w, aw);
        ax = fmaf(v1, h1.x, ax); ay = fmaf(v1, h1.y, ay);
        az = fmaf(v1, h1.z, az); aw = fmaf(v1, h1.w, aw);
        ax = fmaf(v2, h2.x, ax); ay = fmaf(v2, h2.y, ay);
        az = fmaf(v2, h2.z, az); aw = fmaf(v2, h2.w, aw);
        ax = fmaf(v3, h3.x, ax); ay = fmaf(v3, h3.y, ay);
        az = fmaf(v3, h3.z, az); aw = fmaf(v3, h3.w, aw);
    }
    for (; e < end; e++) {
        int2 p0 = __ldg(g_epack + e);
        float v0 = __int_as_float(p0.y);
        float4 h0 = *(const float4*)(g_h + (size_t)p0.x * FEAT + off);
        ax = fmaf(v0, h0.x, ax); ay = fmaf(v0, h0.y, ay);
        az = fmaf(v0, h0.z, az); aw = fmaf(v0, h0.w, aw);
    }

    float4 o;
    o.x = fmaxf(ax, 0.f);
    o.y = fmaxf(ay, 0.f);
    o.z = fmaxf(az, 0.f);
    o.w = fmaxf(aw, 0.f);
    *(float4*)(out + (size_t)row * FEAT + off) = o;
}

// ---------------------------------------------------------------------------
extern "C" void kernel_launch(void* const* d_in, const int* in_sizes, int n_in,
                              void* d_out, int out_size) {
    const float* x     = (const float*)d_in[0];
    const int*   arows = (const int*)  d_in[1];
    const int*   acols = (const int*)  d_in[2];
    const float* avals = (const float*)d_in[3];
    const float* W     = (const float*)d_in[4];
    const float* bias  = (const float*)d_in[5];
    const float* ct    = (const float*)d_in[6];
    float* out = (float*)d_out;

    int M = in_sizes[0] / FEAT;
    int E = in_sizes[1];
    int nb = (M + 1023) / 1024;   // <= 98 for M=100000

    prep_kernel<<<1, 256>>>(bias, ct);

    // CSR build (independent of GEMM result)
    zero_deg_kernel<<<(M + 255) / 256, 256>>>(M);
    hist_kernel<<<592, 256>>>(arows, E);
    scan1_kernel<<<nb, 1024>>>(M);
    scan2_kernel<<<1, NBMAX>>>(nb, M, E);
    scan3_kernel<<<nb, 1024>>>(M);
    scatter_kernel<<<592, 256>>>(arows, acols, avals, E);

    dim3 ggrid(2, (M + 127) / 128);
    gemm_kernel<<<ggrid, 256>>>(x, W, M);

    hyp_kernel<<<(M + 7) / 8, 256>>>(M);

    int rblocks = (M + 7) / 8;                   // 8 warps/block, 1 warp/row
    row_kernel<<<rblocks, 256>>>(out, M, 0);
    row_kernel<<<rblocks, 256>>>(out, M, 1);
}